// round 1
// baseline (speedup 1.0000x reference)
#include <cuda_runtime.h>

// Problem constants: logits (B=2,1,160,160,160) f32, target same i32, area_table (256) f32.
#define DB 160
#define HB 160
#define WB 160
#define NB 2
#define NTOT (NB*DB*HB*WB)              // 8,192,000
#define CHUNK 8                          // elements per thread along W
#define WCHUNKS (WB/CHUNK)               // 20
#define NCHUNKS (NB*DB*HB*WCHUNKS)       // 1,024,000
#define TPB 256
#define NBLOCKS (NCHUNKS/TPB)            // 4000 exactly

// acc[0]=sum (1+w)*bce, acc[1]=sum p, acc[2]=sum p*t, acc[3]=sum t
__device__ double g_acc[4];

__global__ void init_acc_kernel() {
    if (threadIdx.x < 4) g_acc[threadIdx.x] = 0.0;
}

__global__ __launch_bounds__(TPB) void loss_main_kernel(
    const float* __restrict__ logits,
    const int*   __restrict__ target,
    const float* __restrict__ area_table)
{
    __shared__ float s_area[256];
    s_area[threadIdx.x] = area_table[threadIdx.x];
    __syncthreads();

    const int c  = blockIdx.x * TPB + threadIdx.x;   // chunk id, always < NCHUNKS
    const int wi = c % WCHUNKS;
    int r        = c / WCHUNKS;
    const int h  = r % HB;
    r            = r / HB;
    const int d  = r % DB;
    const int b  = r / DB;

    const int base = ((b * DB + d) * HB + h) * WB + wi * CHUNK;

    // ---- loads ----
    const float4 l0 = *(const float4*)(logits + base);
    const float4 l1 = *(const float4*)(logits + base + 4);
    float x[8] = {l0.x, l0.y, l0.z, l0.w, l1.x, l1.y, l1.z, l1.w};

    const bool tailok = (wi < WCHUNKS - 1);

    int t00[9];
    {
        int4 a = *(const int4*)(target + base);
        int4 bb = *(const int4*)(target + base + 4);
        t00[0]=a.x; t00[1]=a.y; t00[2]=a.z; t00[3]=a.w;
        t00[4]=bb.x; t00[5]=bb.y; t00[6]=bb.z; t00[7]=bb.w;
        t00[8] = tailok ? target[base + 8] : 0;
    }

    const bool interior = (d < DB - 1) && (h < HB - 1);
    int t01[9], t10[9], t11[9];
    #pragma unroll
    for (int i = 0; i < 9; i++) { t01[i]=0; t10[i]=0; t11[i]=0; }
    if (interior) {
        const int b01 = base + WB;           // (d, h+1)
        const int b10 = base + HB * WB;      // (d+1, h)
        const int b11 = b10 + WB;            // (d+1, h+1)
        int4 a, bb;
        a = *(const int4*)(target + b01); bb = *(const int4*)(target + b01 + 4);
        t01[0]=a.x; t01[1]=a.y; t01[2]=a.z; t01[3]=a.w;
        t01[4]=bb.x; t01[5]=bb.y; t01[6]=bb.z; t01[7]=bb.w;
        t01[8] = tailok ? target[b01 + 8] : 0;
        a = *(const int4*)(target + b10); bb = *(const int4*)(target + b10 + 4);
        t10[0]=a.x; t10[1]=a.y; t10[2]=a.z; t10[3]=a.w;
        t10[4]=bb.x; t10[5]=bb.y; t10[6]=bb.z; t10[7]=bb.w;
        t10[8] = tailok ? target[b10 + 8] : 0;
        a = *(const int4*)(target + b11); bb = *(const int4*)(target + b11 + 4);
        t11[0]=a.x; t11[1]=a.y; t11[2]=a.z; t11[3]=a.w;
        t11[4]=bb.x; t11[5]=bb.y; t11[6]=bb.z; t11[7]=bb.w;
        t11[8] = tailok ? target[b11 + 8] : 0;
    }

    // ---- per-element math ----
    float acc_wbce = 0.f, acc_p = 0.f, acc_pt = 0.f, acc_t = 0.f;
    #pragma unroll
    for (int e = 0; e < 8; e++) {
        const float xv = x[e];
        const float tf = (float)t00[e];
        const float ex = __expf(-fabsf(xv));       // in (0,1]
        const float l1p = log1pf(ex);
        const float bce = fmaxf(xv, 0.f) - xv * tf + l1p;
        const float p = (xv >= 0.f ? 1.f : ex) * __frcp_rn(1.f + ex);

        float wa = 0.f;
        if (interior && (wi * CHUNK + e) < (WB - 1)) {
            const int code = 128 * t00[e] + 64 * t00[e + 1]
                           +  32 * t01[e] + 16 * t01[e + 1]
                           +   8 * t10[e] +  4 * t10[e + 1]
                           +   2 * t11[e] +  1 * t11[e + 1];
            wa = s_area[code];
        }
        acc_wbce += (1.f + wa) * bce;
        acc_p    += p;
        acc_pt   += p * tf;
        acc_t    += tf;
    }

    // ---- block reduction (float within block, double atomics per block) ----
    #pragma unroll
    for (int off = 16; off > 0; off >>= 1) {
        acc_wbce += __shfl_xor_sync(0xffffffffu, acc_wbce, off);
        acc_p    += __shfl_xor_sync(0xffffffffu, acc_p,    off);
        acc_pt   += __shfl_xor_sync(0xffffffffu, acc_pt,   off);
        acc_t    += __shfl_xor_sync(0xffffffffu, acc_t,    off);
    }

    __shared__ float s_red[4][TPB / 32];
    const int lane = threadIdx.x & 31;
    const int warp = threadIdx.x >> 5;
    if (lane == 0) {
        s_red[0][warp] = acc_wbce;
        s_red[1][warp] = acc_p;
        s_red[2][warp] = acc_pt;
        s_red[3][warp] = acc_t;
    }
    __syncthreads();
    if (warp == 0) {
        const int nw = TPB / 32;
        float v0 = (lane < nw) ? s_red[0][lane] : 0.f;
        float v1 = (lane < nw) ? s_red[1][lane] : 0.f;
        float v2 = (lane < nw) ? s_red[2][lane] : 0.f;
        float v3 = (lane < nw) ? s_red[3][lane] : 0.f;
        #pragma unroll
        for (int off = 4; off > 0; off >>= 1) {
            v0 += __shfl_xor_sync(0xffffffffu, v0, off);
            v1 += __shfl_xor_sync(0xffffffffu, v1, off);
            v2 += __shfl_xor_sync(0xffffffffu, v2, off);
            v3 += __shfl_xor_sync(0xffffffffu, v3, off);
        }
        if (lane == 0) {
            atomicAdd(&g_acc[0], (double)v0);
            atomicAdd(&g_acc[1], (double)v1);
            atomicAdd(&g_acc[2], (double)v2);
            atomicAdd(&g_acc[3], (double)v3);
        }
    }
}

__global__ void finalize_kernel(float* __restrict__ out) {
    const double N = (double)NTOT;
    const double wbce = g_acc[0] / N;
    const double dice = 1.0 - (2.0 * g_acc[2] + 1.0) / (g_acc[1] + g_acc[3] + 1.0);
    out[0] = (float)(wbce + dice);
}

extern "C" void kernel_launch(void* const* d_in, const int* in_sizes, int n_in,
                              void* d_out, int out_size) {
    const float* logits     = (const float*)d_in[0];
    const int*   target     = (const int*)d_in[1];
    const float* area_table = (const float*)d_in[2];
    float* out = (float*)d_out;

    init_acc_kernel<<<1, 32>>>();
    loss_main_kernel<<<NBLOCKS, TPB>>>(logits, target, area_table);
    finalize_kernel<<<1, 1>>>(out);
}